// round 7
// baseline (speedup 1.0000x reference)
#include <cuda_runtime.h>
#include <cstdint>

// Per-row nonlinear scan, w[k+1] = w[k] + a/w[k] - b*x[k], 32768 rows x 1024.
// One thread per row; 32x33 smem transpose tiles (pad -> conflict-free).
//
// ARITHMETIC (FROZEN; rel_err 0.0 in R1/R2/R5/R6):
//     w = w + a / w - b * xv;        // IEEE div, default rounding
// rcp.approx diverges (R3: 2.05 rel_err, chaotic map). Hand-expanded div is
// slower (R5). Do not touch.
//
// Round 7 = R6's store-fusion done right:
//  - tile 0 peeled -> fused store blocks are UNCONDITIONAL (no branches in
//    the unrolled divide chain; R6's 8 runtime branches caused the regression)
//  - pointer-swapped double buffers (no dynamic [cur] indexing)
//  - register depth-1 input prefetch (R2's proven scheme)
//  - 2 syncwarps per tile

#define N_COLS 1024
#define WPB 4
#define TILE 32
#define NT (N_COLS / TILE)   // 32

__global__ __launch_bounds__(WPB * 32)
void DDK_77644418777662_kernel(const float* __restrict__ x,
                               const float* __restrict__ alpha,
                               const float* __restrict__ beta,
                               float* __restrict__ out,
                               int rows) {
    __shared__ float shA[WPB][TILE][TILE + 1];
    __shared__ float shB[WPB][TILE][TILE + 1];

    const int warp = threadIdx.x >> 5;
    const int lane = threadIdx.x & 31;
    const int rowBase = (blockIdx.x * WPB + warp) * TILE;
    if (rowBase >= rows) return;

    const float a = __ldg(alpha);
    const float b = __ldg(beta);

    const float* xrow = x + (size_t)rowBase * N_COLS;
    float* orow       = out + (size_t)rowBase * N_COLS;

    const int tr = lane >> 3;   // 0..3
    const int tc = lane & 7;    // 0..7

    // per-warp base pointers (rows of TILE+1 floats)
    float (*cur)[TILE + 1] = shA[warp];
    float (*prv)[TILE + 1] = shB[warp];

    float4 pf[8];

    // ================= prologue: tile 0 =================
    #pragma unroll
    for (int g = 0; g < 8; g++)
        pf[g] = *(const float4*)(xrow + (size_t)(g * 4 + tr) * N_COLS + tc * 4);
    #pragma unroll
    for (int g = 0; g < 8; g++) {
        const int r = g * 4 + tr;
        cur[r][tc * 4 + 0] = pf[g].x;
        cur[r][tc * 4 + 1] = pf[g].y;
        cur[r][tc * 4 + 2] = pf[g].z;
        cur[r][tc * 4 + 3] = pf[g].w;
    }
    __syncwarp();

    float w = 1.0f;

    // tile 0: prefetch tile 1, compute (NO fused stores -- nothing to store yet)
    #pragma unroll
    for (int g = 0; g < 8; g++)
        pf[g] = *(const float4*)(xrow + (size_t)(g * 4 + tr) * N_COLS + TILE + tc * 4);
    #pragma unroll
    for (int j = 0; j < TILE; j++) {
        const float xv = cur[lane][j];
        cur[lane][j] = w;
        w = w + a / w - b * xv;          // FROZEN
    }
    __syncwarp();
    // commit tile 1 inputs into prv
    #pragma unroll
    for (int g = 0; g < 8; g++) {
        const int r = g * 4 + tr;
        prv[r][tc * 4 + 0] = pf[g].x;
        prv[r][tc * 4 + 1] = pf[g].y;
        prv[r][tc * 4 + 2] = pf[g].z;
        prv[r][tc * 4 + 3] = pf[g].w;
    }
    __syncwarp();
    // swap: cur now holds tile-0 OUTPUTS (to store), prv holds tile-1 inputs
    { float (*t)[TILE + 1] = cur; cur = prv; prv = t; }

    // ================= main loop: tiles 1..NT-1 =================
    // invariant at top: cur = inputs of tile t, prv = outputs of tile t-1
    for (int t = 1; t < NT; t++) {
        // issue tile t+1's LDGs (fly during the chain)
        if (t + 1 < NT) {
            const int c0 = (t + 1) * TILE;
            #pragma unroll
            for (int g = 0; g < 8; g++)
                pf[g] = *(const float4*)(xrow + (size_t)(g * 4 + tr) * N_COLS
                                         + c0 + tc * 4);
        }

        // 32-step chain with UNCONDITIONAL fused stores of tile t-1
        const int cprev = (t - 1) * TILE;
        #pragma unroll
        for (int j = 0; j < TILE; j++) {
            const float xv = cur[lane][j];
            cur[lane][j] = w;
            w = w + a / w - b * xv;      // FROZEN
            if ((j & 3) == 0) {          // compile-time: 8 store blocks, no branch
                const int g = j >> 2;
                const int r = g * 4 + tr;
                float4 v;
                v.x = prv[r][tc * 4 + 0];
                v.y = prv[r][tc * 4 + 1];
                v.z = prv[r][tc * 4 + 2];
                v.w = prv[r][tc * 4 + 3];
                *(float4*)(orow + (size_t)r * N_COLS + cprev + tc * 4) = v;
            }
        }
        __syncwarp();   // chain writes to cur + reads of prv complete warp-wide

        // commit tile t+1 inputs into prv (now free)
        if (t + 1 < NT) {
            #pragma unroll
            for (int g = 0; g < 8; g++) {
                const int r = g * 4 + tr;
                prv[r][tc * 4 + 0] = pf[g].x;
                prv[r][tc * 4 + 1] = pf[g].y;
                prv[r][tc * 4 + 2] = pf[g].z;
                prv[r][tc * 4 + 3] = pf[g].w;
            }
        }
        __syncwarp();
        { float (*tmp)[TILE + 1] = cur; cur = prv; prv = tmp; }
    }

    // ================= epilogue: store last tile's outputs (in prv) ========
    {
        const int c0 = (NT - 1) * TILE;
        #pragma unroll
        for (int g = 0; g < 8; g++) {
            const int r = g * 4 + tr;
            float4 v;
            v.x = prv[r][tc * 4 + 0];
            v.y = prv[r][tc * 4 + 1];
            v.z = prv[r][tc * 4 + 2];
            v.w = prv[r][tc * 4 + 3];
            *(float4*)(orow + (size_t)r * N_COLS + c0 + tc * 4) = v;
        }
    }
}

extern "C" void kernel_launch(void* const* d_in, const int* in_sizes, int n_in,
                              void* d_out, int out_size) {
    const float* x     = (const float*)d_in[0];
    const float* alpha = (const float*)d_in[1];
    const float* beta  = (const float*)d_in[2];
    float* out         = (float*)d_out;

    const int rows = out_size / N_COLS;                 // 32768
    const int rowsPerBlock = WPB * TILE;                // 128
    const int blocks = (rows + rowsPerBlock - 1) / rowsPerBlock;  // 256

    DDK_77644418777662_kernel<<<blocks, WPB * 32>>>(x, alpha, beta, out, rows);
}